// round 10
// baseline (speedup 1.0000x reference)
#include <cuda_runtime.h>
#include <cuda_bf16.h>

// Problem constants
#define VV   32000
#define DD   32
#define BB   8
#define SS   1024
#define BS   (BB*SS)                 // 8192
#define NVB  125                     // vocab tiles of 256 (125*256 = 32000)
#define NRT  64                      // row tiles of 128   (64*128 = 8192)

// Scratch (static device arrays; no allocation)
__device__ float g_xgates[BS*128];                    // [b,s,4D]  4 MB
__device__ float g_outs[BS*DD];                       // [b,s,D]   1 MB
__device__ __align__(16) __nv_bfloat16 g_fcqh[VV*DD]; // quantized fc_w HALVES (q*0.5, exact bf16), 2 MB
__device__ float g_wihqT[DD*128];                     // quantized w_ih, TRANSPOSED [d][j]
__device__ float g_whhq[128*DD];                      // quantized w_hh, row-major [j][d]
__device__ float g_part[256];                         // partial |.| sums
__device__ float g_scales[4];                         // emb, ih, hh, fc
__device__ unsigned g_prog[8];                        // LSTM steps completed per batch

// ---------------- helpers ----------------
__device__ __forceinline__ float quantw(float w, float s) {
    // clip(round(w/s*2)/2, -1.5, 1.5) * s ; rintf = round-half-even = jnp.round
    float t = __fmul_rn(__fdiv_rn(w, s), 2.0f);
    float q = rintf(t);
    q = fmaxf(-3.0f, fminf(3.0f, q));
    return __fmul_rn(q * 0.5f, s);
}
__device__ __forceinline__ float quant_half(float w, float s) {
    // clip(round(w/s*2),-3,3)*0.5 : the UNscaled quantized value (exact in bf16)
    float t = __fmul_rn(__fdiv_rn(w, s), 2.0f);
    float q = rintf(t);
    q = fmaxf(-3.0f, fminf(3.0f, q));
    return q * 0.5f;
}
__device__ __forceinline__ float sigf(float x) {
    return __fdividef(1.0f, 1.0f + __expf(-x));
}
__device__ __forceinline__ float tanh_f(float x) {
    return __fmaf_rn(2.0f, sigf(2.0f * x), -1.0f);
}
__device__ __forceinline__ unsigned pkbf(float lo, float hi) {
    __nv_bfloat162 h2 = __floats2bfloat162_rn(lo, hi);   // lo -> low half
    return *(unsigned*)&h2;
}
// streaming 8B store (evict-first): logits are write-once, never re-read
__device__ __forceinline__ void stg_cs_f2(float* p, float lo, float hi) {
    asm volatile("st.global.cs.v2.f32 [%0], {%1, %2};" :: "l"(p), "f"(lo), "f"(hi) : "memory");
}
__device__ __forceinline__ void ldsm_x4(unsigned& r0, unsigned& r1, unsigned& r2, unsigned& r3,
                                        unsigned addr) {
    asm volatile("ldmatrix.sync.aligned.m8n8.x4.shared.b16 {%0,%1,%2,%3}, [%4];"
                 : "=r"(r0), "=r"(r1), "=r"(r2), "=r"(r3) : "r"(addr));
}
__device__ __forceinline__ void mma16816(float* c, const unsigned* a, unsigned b0, unsigned b1) {
    asm volatile("mma.sync.aligned.m16n8k16.row.col.f32.bf16.bf16.f32 "
                 "{%0,%1,%2,%3}, {%4,%5,%6,%7}, {%8,%9}, {%0,%1,%2,%3};"
                 : "+f"(c[0]), "+f"(c[1]), "+f"(c[2]), "+f"(c[3])
                 : "r"(a[0]), "r"(a[1]), "r"(a[2]), "r"(a[3]), "r"(b0), "r"(b1));
}

// ---------------- K1: partial abs-sums for emb_w (blocks 0..127) and fc_w (128..255) ----------------
__global__ void k_reduce(const float* __restrict__ emb, const float* __restrict__ fcw) {
    __shared__ float sm[256];
    const int tid = threadIdx.x;
    const float4* w = (blockIdx.x < 128) ? (const float4*)emb : (const float4*)fcw;
    const int lb = blockIdx.x & 127;
    float s = 0.f;
    for (int i = lb * 256 + tid; i < 256000; i += 128 * 256) {
        float4 v = w[i];
        s += (fabsf(v.x) + fabsf(v.y)) + (fabsf(v.z) + fabsf(v.w));
    }
    sm[tid] = s;
    __syncthreads();
    for (int st = 128; st > 0; st >>= 1) {
        if (tid < st) sm[tid] += sm[tid + st];
        __syncthreads();
    }
    if (tid == 0) g_part[blockIdx.x] = sm[0];
}

// ---------------- K2: finalize scales + quantize w_ih (transposed) and w_hh; reset progress ----------------
__global__ void k_final(const float* __restrict__ wih, const float* __restrict__ whh) {
    __shared__ float sm[256];
    __shared__ float sc[4];
    const int t = threadIdx.x;

    if (t < 8) g_prog[t] = 0;   // reset per call (graph replays)

    sm[t] = (t < 128) ? g_part[t] : 0.f;
    __syncthreads();
    for (int st = 128; st > 0; st >>= 1) { if (t < st) sm[t] += sm[t + st]; __syncthreads(); }
    if (t == 0) sc[0] = fmaxf(sm[0] / 1024000.0f * 2.0f, 1e-8f);
    __syncthreads();

    sm[t] = (t < 128) ? g_part[128 + t] : 0.f;
    __syncthreads();
    for (int st = 128; st > 0; st >>= 1) { if (t < st) sm[t] += sm[t + st]; __syncthreads(); }
    if (t == 0) sc[3] = fmaxf(sm[0] / 1024000.0f * 2.0f, 1e-8f);
    __syncthreads();

    {
        float s = 0.f;
        #pragma unroll
        for (int k = 0; k < 16; k++) s += fabsf(wih[t + 256 * k]);
        sm[t] = s;
        __syncthreads();
        for (int st = 128; st > 0; st >>= 1) { if (t < st) sm[t] += sm[t + st]; __syncthreads(); }
        if (t == 0) sc[1] = fmaxf(sm[0] / 4096.0f * 2.0f, 1e-8f);
        __syncthreads();
    }
    {
        float s = 0.f;
        #pragma unroll
        for (int k = 0; k < 16; k++) s += fabsf(whh[t + 256 * k]);
        sm[t] = s;
        __syncthreads();
        for (int st = 128; st > 0; st >>= 1) { if (t < st) sm[t] += sm[t + st]; __syncthreads(); }
        if (t == 0) sc[2] = fmaxf(sm[0] / 4096.0f * 2.0f, 1e-8f);
        __syncthreads();
    }

    for (int k = t; k < 4096; k += 256) {
        int j = k >> 5, d = k & 31;
        g_wihqT[d * 128 + j] = quantw(wih[k], sc[1]);
        g_whhq[k]            = quantw(whh[k], sc[2]);
    }
    if (t < 4) g_scales[t] = sc[t];
}

// ---------------- K3: quantize fc_w -> bf16 half-integer levels ----------------
__global__ void k_fcq(const float* __restrict__ fcw) {
    const int i = blockIdx.x * 256 + threadIdx.x;   // float4 index, 256000 total
    const float s = g_scales[3];
    float4 v = ((const float4*)fcw)[i];
    uint2 o;
    o.x = pkbf(quant_half(v.x, s), quant_half(v.y, s));
    o.y = pkbf(quant_half(v.z, s), quant_half(v.w, s));
    ((uint2*)g_fcqh)[i] = o;
}

// ---------------- K4: x_gates. 256 blocks x 32 tokens; weight column cached in registers ----------------
__global__ void k_xg(const int* __restrict__ x, const float* __restrict__ emb_w,
                     const float* __restrict__ b_ih) {
    __shared__ float es[2][32];            // double-buffered token embedding
    const int tid = threadIdx.x;
    const int base = blockIdx.x * 32;      // first token index for this block

    float wr[32];                          // Wih^T column tid, loaded ONCE
    #pragma unroll
    for (int d = 0; d < 32; d++) wr[d] = g_wihqT[d * 128 + tid];
    const float bi = b_ih[tid];
    const float se = g_scales[0];

    if (tid < 32) {                        // preload token 0
        int tok = x[base];
        es[0][tid] = quantw(emb_w[tok * 32 + tid], se);
    }
    __syncthreads();

    for (int t = 0; t < 32; t++) {
        const int pb = t & 1;
        if (t < 31 && tid < 32) {          // prefetch next token into other buffer
            int tok = x[base + t + 1];
            es[pb ^ 1][tid] = quantw(emb_w[tok * 32 + tid], se);
        }
        float acc = bi;
        #pragma unroll
        for (int d = 0; d < 32; d++) acc = fmaf(es[pb][d], wr[d], acc);  // broadcast LDS
        g_xgates[(base + t) * 128 + tid] = acc;
        __syncthreads();                   // separates this iter's reads from next overwrite
    }
}

// ================== FUSED: LSTM producer blocks (bid 0..7) + FC consumer blocks ==================

__device__ __forceinline__ void lstm_role(int b, const float* __restrict__ b_hh,
                                          float* __restrict__ dout) {
    __shared__ __align__(16) float hsw[4][32];
    __shared__ float tg[2][128];
    const int j = threadIdx.x;
    const int act = (j < 128);
    const int w = (j >> 5) & 3, l = j & 31;

    float wr[32];
    float bh = 0.f;
    if (act) {
        #pragma unroll
        for (int d = 0; d < 32; d++) wr[d] = g_whhq[j * 32 + d];
        bh = b_hh[j];
        hsw[w][l] = 0.f;
    }
    float c = 0.f, h = 0.f;
    const float* xp = g_xgates + b * SS * 128 + j;
    float* op = g_outs + b * SS * 32;
    __syncthreads();

    float xg = act ? xp[0] : 0.f;
    const int tsel = (w == 2);
    for (int s = 0; s < SS; s++) {
        float xgn = (act && s < SS - 1) ? xp[(s + 1) * 128] : 0.f;
        const int pb = s & 1;

        if (act) {
            float a0 = xg + bh, a1 = 0.f, a2 = 0.f, a3 = 0.f;
            const float4* h4 = (const float4*)hsw[w];
            #pragma unroll
            for (int k = 0; k < 8; k++) {
                float4 hv = h4[k];
                a0 = fmaf(hv.x, wr[4 * k + 0], a0);
                a1 = fmaf(hv.y, wr[4 * k + 1], a1);
                a2 = fmaf(hv.z, wr[4 * k + 2], a2);
                a3 = fmaf(hv.w, wr[4 * k + 3], a3);
            }
            float gate = (a0 + a1) + (a2 + a3);
            tg[pb][j] = tsel ? tanh_f(gate) : sigf(gate);
        }
        __syncthreads();

        if (act) {
            float ti = tg[pb][l], tf = tg[pb][l + 32], g2 = tg[pb][l + 64], to = tg[pb][l + 96];
            c = fmaf(tf, c, ti * g2);
            h = to * tanh_f(c);
            hsw[w][l] = h;
            if (w == 0) op[s * 32 + l] = h;
        }
        if ((s & 127) == 127) {            // publish progress (safe pattern)
            __threadfence();
            __syncthreads();
            if (j == 0) *(volatile unsigned*)&g_prog[b] = (unsigned)(s + 1);
        }
        __syncwarp();
        xg = xgn;
    }
    if (j < 32) {
        dout[262144000 + b * 32 + j] = h;   // hT
        dout[262144256 + b * 32 + j] = c;   // cT
    }
}

// FC role: one 256-vocab x 128-row tile via bf16 split-precision mma.sync.
// Smem rows padded to 80B -> conflict-free LDSM. B tiles software-pipelined.
__device__ __forceinline__ void fc_role(int f, const float* __restrict__ fcb,
                                        float* __restrict__ logits) {
    __shared__ __align__(16) __nv_bfloat16 qs[256][40];   // Q tile  (cols 0-31 used)
    __shared__ __align__(16) __nv_bfloat16 ah[128][40];   // A hi
    __shared__ __align__(16) __nv_bfloat16 al[128][40];   // A lo
    const int tid = threadIdx.x;
    const int lane = tid & 31, w = tid >> 5;
    const int vb    = f % NVB;
    const int tile  = f / NVB;
    const int batch = tile & 7;
    const int stile = tile >> 3;
    const int vbase = vb * 256;
    const int rbase = batch * 1024 + stile * 128;

    // wait until this batch's LSTM has produced rows [stile*128, +128)
    if (tid == 0) {
        const unsigned need = (unsigned)((stile + 1) * 128);
        while (*(volatile unsigned*)&g_prog[batch] < need) __nanosleep(200);
        __threadfence();
    }
    __syncthreads();

    // ---- stage Q tile: thread t copies row (vbase+t), 64B ----
    {
        const uint4* src = (const uint4*)(g_fcqh + (vbase + tid) * 32);
        uint4* dst = (uint4*)&qs[tid][0];
        #pragma unroll
        for (int k = 0; k < 4; k++) dst[k] = src[k];
    }
    // ---- stage A tile with hi/lo split: thread t -> row tid>>1, half tid&1 ----
    {
        const int r = tid >> 1, hh = tid & 1;
        const float4* src = (const float4*)(g_outs + (rbase + r) * 32 + 16 * hh);
        unsigned hp[8], lp[8];
        #pragma unroll
        for (int q = 0; q < 4; q++) {
            float4 v = src[q];
            float h0 = __bfloat162float(__float2bfloat16(v.x));
            float h1 = __bfloat162float(__float2bfloat16(v.y));
            float h2 = __bfloat162float(__float2bfloat16(v.z));
            float h3 = __bfloat162float(__float2bfloat16(v.w));
            hp[2*q+0] = pkbf(h0, h1);
            hp[2*q+1] = pkbf(h2, h3);
            lp[2*q+0] = pkbf(v.x - h0, v.y - h1);
            lp[2*q+1] = pkbf(v.z - h2, v.w - h3);
        }
        uint4* dh = (uint4*)&ah[r][16 * hh];
        uint4* dl = (uint4*)&al[r][16 * hh];
        dh[0] = make_uint4(hp[0], hp[1], hp[2], hp[3]);
        dh[1] = make_uint4(hp[4], hp[5], hp[6], hp[7]);
        dl[0] = make_uint4(lp[0], lp[1], lp[2], lp[3]);
        dl[1] = make_uint4(lp[4], lp[5], lp[6], lp[7]);
    }
    __syncthreads();

    const float s = g_scales[3];

    // ---- A fragments for this warp's 16-row tile (rows 16w..16w+15) ----
    // ldmatrix x4 matrix i <- addresses from lanes 8i..8i+7
    // m0: rows 0-7 k0-7 | m1: rows 8-15 k0-7 | m2: rows 0-7 k8-15 | m3: rows 8-15 k8-15
    unsigned afh[2][4], afl[2][4];
    {
        const int m = lane >> 3, lr = lane & 7;
        const int row = 16 * w + (m & 1) * 8 + lr;
        const int kc  = (m >> 1) * 8;
        unsigned ah0 = (unsigned)__cvta_generic_to_shared(&ah[row][kc]);
        unsigned ah1 = (unsigned)__cvta_generic_to_shared(&ah[row][kc + 16]);
        unsigned al0 = (unsigned)__cvta_generic_to_shared(&al[row][kc]);
        unsigned al1 = (unsigned)__cvta_generic_to_shared(&al[row][kc + 16]);
        ldsm_x4(afh[0][0], afh[0][1], afh[0][2], afh[0][3], ah0);
        ldsm_x4(afh[1][0], afh[1][1], afh[1][2], afh[1][3], ah1);
        ldsm_x4(afl[0][0], afl[0][1], afl[0][2], afl[0][3], al0);
        ldsm_x4(afl[1][0], afl[1][1], afl[1][2], afl[1][3], al1);
    }

    // B lane address base: row = nt*8 + (lane&7), kcol = (lane>>3)*8
    unsigned qaddr = (unsigned)__cvta_generic_to_shared(&qs[lane & 7][(lane >> 3) * 8]);

    const int g = lane >> 2, t4 = lane & 3;
    const int row0 = rbase + 16 * w + g;
    float* out0 = logits + row0 * VV + vbase + 2 * t4;
    const float* bias0 = fcb + vbase + 2 * t4;

    // software pipeline: prefetch B tile nt+1 during MMAs of tile nt
    unsigned b0, b1, b2, b3;
    ldsm_x4(b0, b1, b2, b3, qaddr);
    #pragma unroll 4
    for (int nt = 0; nt < 32; nt++) {
        unsigned n0 = 0, n1 = 0, n2 = 0, n3 = 0;   // init: no UB on final iter
        if (nt < 31) {
            ldsm_x4(n0, n1, n2, n3, qaddr + 8 * 80);
        }
        qaddr += 8 * 80;

        float acc[4] = {0.f, 0.f, 0.f, 0.f};
        mma16816(acc, afh[0], b0, b1);   // hi, k0-15
        mma16816(acc, afh[1], b2, b3);   // hi, k16-31
        mma16816(acc, afl[0], b0, b1);   // lo, k0-15
        mma16816(acc, afl[1], b2, b3);   // lo, k16-31

        const float2 bb = *(const float2*)(bias0 + nt * 8);
        float o00 = fmaf(s, acc[0], bb.x), o01 = fmaf(s, acc[1], bb.y);
        float o10 = fmaf(s, acc[2], bb.x), o11 = fmaf(s, acc[3], bb.y);
        stg_cs_f2(out0 + nt * 8, o00, o01);                // row g,   cols 2t4,2t4+1
        stg_cs_f2(out0 + 8 * VV + nt * 8, o10, o11);       // row g+8

        b0 = n0; b1 = n1; b2 = n2; b3 = n3;
    }
}

__global__ void __launch_bounds__(256) k_fused(const float* __restrict__ b_hh,
                                               const float* __restrict__ fcb,
                                               float* __restrict__ out) {
    const int bid = blockIdx.x;
    if (bid < BB) { lstm_role(bid, b_hh, out); return; }
    fc_role(bid - BB, fcb, out);
}

// ---------------- launch ----------------
extern "C" void kernel_launch(void* const* d_in, const int* in_sizes, int n_in,
                              void* d_out, int out_size) {
    const int*   x     = (const int*)  d_in[0];
    const float* emb_w = (const float*)d_in[1];
    const float* w_ih  = (const float*)d_in[2];
    const float* b_ih  = (const float*)d_in[3];
    const float* w_hh  = (const float*)d_in[4];
    const float* b_hh  = (const float*)d_in[5];
    const float* fc_w  = (const float*)d_in[6];
    const float* fc_b  = (const float*)d_in[7];
    float* out = (float*)d_out;

    k_reduce<<<256, 256>>>(emb_w, fc_w);
    k_final<<<1, 256>>>(w_ih, w_hh);            // also resets g_prog
    k_fcq<<<1000, 256>>>(fc_w);
    k_xg<<<256, 128>>>(x, emb_w, b_ih);
    k_fused<<<BB + NVB * NRT, 256>>>(b_hh, fc_b, out);
}

// round 15
// speedup vs baseline: 1.2205x; 1.2205x over previous
#include <cuda_runtime.h>
#include <cuda_bf16.h>

// Problem constants
#define VV   32000
#define DD   32
#define BB   8
#define SS   1024
#define BS   (BB*SS)                 // 8192
#define NVB  125                     // vocab tiles of 256 (125*256 = 32000)
#define NRT  64                      // row tiles of 128   (64*128 = 8192)
#define NTILES (NVB*NRT)             // 8000

// Scratch (static device arrays; no allocation)
__device__ float g_xgates[BS*128];                    // [b,s,4D]  4 MB
__device__ float g_outs[BS*DD];                       // [b,s,D]   1 MB
__device__ __align__(16) __nv_bfloat16 g_fcqh[VV*DD]; // quantized fc_w HALVES (q*0.5, exact bf16), 2 MB
__device__ float g_wihqT[DD*128];                     // quantized w_ih, TRANSPOSED [d][j]
__device__ float g_whhq[128*DD];                      // quantized w_hh, row-major [j][d]
__device__ float g_part[256];                         // partial |.| sums
__device__ float g_scales[4];                         // emb, ih, hh, fc
__device__ unsigned g_prog[8];                        // LSTM steps completed per batch
__device__ int      g_lstm_smid[8];                   // SMs hosting LSTM blocks
__device__ unsigned g_smid_ready;                     // count of published smids
__device__ unsigned g_tilectr;                        // FC tile work queue

// ---------------- helpers ----------------
__device__ __forceinline__ float quantw(float w, float s) {
    float t = __fmul_rn(__fdiv_rn(w, s), 2.0f);
    float q = rintf(t);
    q = fmaxf(-3.0f, fminf(3.0f, q));
    return __fmul_rn(q * 0.5f, s);
}
__device__ __forceinline__ float quant_half(float w, float s) {
    float t = __fmul_rn(__fdiv_rn(w, s), 2.0f);
    float q = rintf(t);
    q = fmaxf(-3.0f, fminf(3.0f, q));
    return q * 0.5f;
}
__device__ __forceinline__ float sigf(float x) {
    return __fdividef(1.0f, 1.0f + __expf(-x));
}
__device__ __forceinline__ float tanh_f(float x) {
    return __fmaf_rn(2.0f, sigf(2.0f * x), -1.0f);
}
__device__ __forceinline__ unsigned pkbf(float lo, float hi) {
    __nv_bfloat162 h2 = __floats2bfloat162_rn(lo, hi);
    return *(unsigned*)&h2;
}
__device__ __forceinline__ void stg_cs_f2(float* p, float lo, float hi) {
    asm volatile("st.global.cs.v2.f32 [%0], {%1, %2};" :: "l"(p), "f"(lo), "f"(hi) : "memory");
}
__device__ __forceinline__ void ldsm_x4(unsigned& r0, unsigned& r1, unsigned& r2, unsigned& r3,
                                        unsigned addr) {
    asm volatile("ldmatrix.sync.aligned.m8n8.x4.shared.b16 {%0,%1,%2,%3}, [%4];"
                 : "=r"(r0), "=r"(r1), "=r"(r2), "=r"(r3) : "r"(addr));
}
__device__ __forceinline__ void mma16816(float* c, const unsigned* a, unsigned b0, unsigned b1) {
    asm volatile("mma.sync.aligned.m16n8k16.row.col.f32.bf16.bf16.f32 "
                 "{%0,%1,%2,%3}, {%4,%5,%6,%7}, {%8,%9}, {%0,%1,%2,%3};"
                 : "+f"(c[0]), "+f"(c[1]), "+f"(c[2]), "+f"(c[3])
                 : "r"(a[0]), "r"(a[1]), "r"(a[2]), "r"(a[3]), "r"(b0), "r"(b1));
}
__device__ __forceinline__ unsigned read_smid() {
    unsigned sm; asm("mov.u32 %0, %%smid;" : "=r"(sm)); return sm;
}

// ---------------- K1: partial abs-sums for emb_w (blocks 0..127) and fc_w (128..255) ----------------
__global__ void k_reduce(const float* __restrict__ emb, const float* __restrict__ fcw) {
    __shared__ float sm[256];
    const int tid = threadIdx.x;
    const float4* w = (blockIdx.x < 128) ? (const float4*)emb : (const float4*)fcw;
    const int lb = blockIdx.x & 127;
    float s = 0.f;
    for (int i = lb * 256 + tid; i < 256000; i += 128 * 256) {
        float4 v = w[i];
        s += (fabsf(v.x) + fabsf(v.y)) + (fabsf(v.z) + fabsf(v.w));
    }
    sm[tid] = s;
    __syncthreads();
    for (int st = 128; st > 0; st >>= 1) {
        if (tid < st) sm[tid] += sm[tid + st];
        __syncthreads();
    }
    if (tid == 0) g_part[blockIdx.x] = sm[0];
}

// ---------------- K2: finalize scales + quantize small mats; reset sync state ----------------
__global__ void k_final(const float* __restrict__ wih, const float* __restrict__ whh) {
    __shared__ float sm[256];
    __shared__ float sc[4];
    const int t = threadIdx.x;

    if (t < 8) g_prog[t] = 0;
    if (t == 8) g_smid_ready = 0;
    if (t == 9) g_tilectr = 0;

    sm[t] = (t < 128) ? g_part[t] : 0.f;
    __syncthreads();
    for (int st = 128; st > 0; st >>= 1) { if (t < st) sm[t] += sm[t + st]; __syncthreads(); }
    if (t == 0) sc[0] = fmaxf(sm[0] / 1024000.0f * 2.0f, 1e-8f);
    __syncthreads();

    sm[t] = (t < 128) ? g_part[128 + t] : 0.f;
    __syncthreads();
    for (int st = 128; st > 0; st >>= 1) { if (t < st) sm[t] += sm[t + st]; __syncthreads(); }
    if (t == 0) sc[3] = fmaxf(sm[0] / 1024000.0f * 2.0f, 1e-8f);
    __syncthreads();

    {
        float s = 0.f;
        #pragma unroll
        for (int k = 0; k < 16; k++) s += fabsf(wih[t + 256 * k]);
        sm[t] = s;
        __syncthreads();
        for (int st = 128; st > 0; st >>= 1) { if (t < st) sm[t] += sm[t + st]; __syncthreads(); }
        if (t == 0) sc[1] = fmaxf(sm[0] / 4096.0f * 2.0f, 1e-8f);
        __syncthreads();
    }
    {
        float s = 0.f;
        #pragma unroll
        for (int k = 0; k < 16; k++) s += fabsf(whh[t + 256 * k]);
        sm[t] = s;
        __syncthreads();
        for (int st = 128; st > 0; st >>= 1) { if (t < st) sm[t] += sm[t + st]; __syncthreads(); }
        if (t == 0) sc[2] = fmaxf(sm[0] / 4096.0f * 2.0f, 1e-8f);
        __syncthreads();
    }

    for (int k = t; k < 4096; k += 256) {
        int j = k >> 5, d = k & 31;
        g_wihqT[d * 128 + j] = quantw(wih[k], sc[1]);
        g_whhq[k]            = quantw(whh[k], sc[2]);
    }
    if (t < 4) g_scales[t] = sc[t];
}

// ---------------- K3 (merged): blocks 0..999 quantize fc_w; blocks 1000..2023 compute x_gates ----------------
__global__ void __launch_bounds__(256) k_prep(const float* __restrict__ fcw,
                                              const int* __restrict__ x,
                                              const float* __restrict__ emb_w,
                                              const float* __restrict__ b_ih) {
    const int tid = threadIdx.x;
    if (blockIdx.x < 1000) {
        const int i = blockIdx.x * 256 + tid;   // float4 index, 256000 total
        const float s = g_scales[3];
        float4 v = ((const float4*)fcw)[i];
        uint2 o;
        o.x = pkbf(quant_half(v.x, s), quant_half(v.y, s));
        o.y = pkbf(quant_half(v.z, s), quant_half(v.w, s));
        ((uint2*)g_fcqh)[i] = o;
        return;
    }
    // xg role: 8 tokens per block, all embeddings preloaded (MLP=8), no in-loop barriers
    __shared__ float es[8][32];
    const int base = (blockIdx.x - 1000) * 8;
    {
        const int slot = tid >> 5, d = tid & 31;   // 256 threads = 8x32 exactly
        int tok = x[base + slot];
        es[slot][d] = quantw(emb_w[tok * 32 + d], g_scales[0]);
    }
    const int j = tid & 127;        // gate index
    const int grp = tid >> 7;       // 0: tokens 0-3, 1: tokens 4-7
    float wr[32];
    #pragma unroll
    for (int d = 0; d < 32; d++) wr[d] = g_wihqT[d * 128 + j];
    const float bi = b_ih[j];
    __syncthreads();
    #pragma unroll
    for (int t = 0; t < 4; t++) {
        const int tok = grp * 4 + t;
        float acc = bi;
        #pragma unroll
        for (int d = 0; d < 32; d++) acc = fmaf(es[tok][d], wr[d], acc);
        g_xgates[(base + tok) * 128 + j] = acc;
    }
}

// ================== FUSED: LSTM producer blocks (bid 0..7) + persistent FC workers ==================

__device__ __forceinline__ void lstm_role(int b, const float* __restrict__ b_hh,
                                          float* __restrict__ dout) {
    __shared__ __align__(16) float hsw[4][32];
    __shared__ float tg[2][128];
    const int j = threadIdx.x;
    const int act = (j < 128);
    const int w = (j >> 5) & 3, l = j & 31;

    if (j == 0) {                      // publish my SM so FC workers avoid it
        g_lstm_smid[b] = (int)read_smid();
        __threadfence();
        atomicAdd(&g_smid_ready, 1u);
    }

    float wr[32];
    float bh = 0.f;
    if (act) {
        #pragma unroll
        for (int d = 0; d < 32; d++) wr[d] = g_whhq[j * 32 + d];
        bh = b_hh[j];
        hsw[w][l] = 0.f;
    }
    float c = 0.f, h = 0.f;
    const float* xp = g_xgates + b * SS * 128 + j;
    float* op = g_outs + b * SS * 32;
    __syncthreads();

    float xg = act ? xp[0] : 0.f;
    const int tsel = (w == 2);
    for (int s = 0; s < SS; s++) {
        float xgn = (act && s < SS - 1) ? xp[(s + 1) * 128] : 0.f;
        const int pb = s & 1;

        if (act) {
            float a0 = xg + bh, a1 = 0.f, a2 = 0.f, a3 = 0.f;
            const float4* h4 = (const float4*)hsw[w];
            #pragma unroll
            for (int k = 0; k < 8; k++) {
                float4 hv = h4[k];
                a0 = fmaf(hv.x, wr[4 * k + 0], a0);
                a1 = fmaf(hv.y, wr[4 * k + 1], a1);
                a2 = fmaf(hv.z, wr[4 * k + 2], a2);
                a3 = fmaf(hv.w, wr[4 * k + 3], a3);
            }
            float gate = (a0 + a1) + (a2 + a3);
            tg[pb][j] = tsel ? tanh_f(gate) : sigf(gate);
        }
        __syncthreads();

        if (act) {
            float ti = tg[pb][l], tf = tg[pb][l + 32], g2 = tg[pb][l + 64], to = tg[pb][l + 96];
            c = fmaf(tf, c, ti * g2);
            h = to * tanh_f(c);
            hsw[w][l] = h;
            if (w == 0) op[s * 32 + l] = h;
        }
        if ((s & 127) == 127) {            // publish progress (safe pattern)
            __threadfence();
            __syncthreads();
            if (j == 0) *(volatile unsigned*)&g_prog[b] = (unsigned)(s + 1);
        }
        __syncwarp();
        xg = xgn;
    }
    if (j < 32) {
        dout[262144000 + b * 32 + j] = h;   // hT
        dout[262144256 + b * 32 + j] = c;   // cT
    }
}

// One 256-vocab x 128-row tile via bf16 split-precision mma.sync.
__device__ __forceinline__ void fc_tile(int f, const float* __restrict__ fcb,
                                        float* __restrict__ logits) {
    __shared__ __align__(16) __nv_bfloat16 qs[256][40];
    __shared__ __align__(16) __nv_bfloat16 ah[128][40];
    __shared__ __align__(16) __nv_bfloat16 al[128][40];
    const int tid = threadIdx.x;
    const int lane = tid & 31, w = tid >> 5;
    const int vb    = f % NVB;
    const int tile  = f / NVB;
    const int batch = tile & 7;
    const int stile = tile >> 3;
    const int vbase = vb * 256;
    const int rbase = batch * 1024 + stile * 128;

    if (tid == 0) {
        const unsigned need = (unsigned)((stile + 1) * 128);
        while (*(volatile unsigned*)&g_prog[batch] < need) __nanosleep(200);
        __threadfence();
    }
    __syncthreads();

    {
        const uint4* src = (const uint4*)(g_fcqh + (vbase + tid) * 32);
        uint4* dst = (uint4*)&qs[tid][0];
        #pragma unroll
        for (int k = 0; k < 4; k++) dst[k] = src[k];
    }
    {
        const int r = tid >> 1, hh = tid & 1;
        const float4* src = (const float4*)(g_outs + (rbase + r) * 32 + 16 * hh);
        unsigned hp[8], lp[8];
        #pragma unroll
        for (int q = 0; q < 4; q++) {
            float4 v = src[q];
            float h0 = __bfloat162float(__float2bfloat16(v.x));
            float h1 = __bfloat162float(__float2bfloat16(v.y));
            float h2 = __bfloat162float(__float2bfloat16(v.z));
            float h3 = __bfloat162float(__float2bfloat16(v.w));
            hp[2*q+0] = pkbf(h0, h1);
            hp[2*q+1] = pkbf(h2, h3);
            lp[2*q+0] = pkbf(v.x - h0, v.y - h1);
            lp[2*q+1] = pkbf(v.z - h2, v.w - h3);
        }
        uint4* dh = (uint4*)&ah[r][16 * hh];
        uint4* dl = (uint4*)&al[r][16 * hh];
        dh[0] = make_uint4(hp[0], hp[1], hp[2], hp[3]);
        dh[1] = make_uint4(hp[4], hp[5], hp[6], hp[7]);
        dl[0] = make_uint4(lp[0], lp[1], lp[2], lp[3]);
        dl[1] = make_uint4(lp[4], lp[5], lp[6], lp[7]);
    }
    __syncthreads();

    const float s = g_scales[3];

    unsigned afh[2][4], afl[2][4];
    {
        const int m = lane >> 3, lr = lane & 7;
        const int row = 16 * w + (m & 1) * 8 + lr;
        const int kc  = (m >> 1) * 8;
        unsigned a0 = (unsigned)__cvta_generic_to_shared(&ah[row][kc]);
        unsigned a1 = (unsigned)__cvta_generic_to_shared(&ah[row][kc + 16]);
        unsigned a2 = (unsigned)__cvta_generic_to_shared(&al[row][kc]);
        unsigned a3 = (unsigned)__cvta_generic_to_shared(&al[row][kc + 16]);
        ldsm_x4(afh[0][0], afh[0][1], afh[0][2], afh[0][3], a0);
        ldsm_x4(afh[1][0], afh[1][1], afh[1][2], afh[1][3], a1);
        ldsm_x4(afl[0][0], afl[0][1], afl[0][2], afl[0][3], a2);
        ldsm_x4(afl[1][0], afl[1][1], afl[1][2], afl[1][3], a3);
    }

    unsigned qaddr = (unsigned)__cvta_generic_to_shared(&qs[lane & 7][(lane >> 3) * 8]);

    const int g = lane >> 2, t4 = lane & 3;
    const int row0 = rbase + 16 * w + g;
    float* out0 = logits + row0 * VV + vbase + 2 * t4;
    const float* bias0 = fcb + vbase + 2 * t4;

    unsigned b0, b1, b2, b3;
    ldsm_x4(b0, b1, b2, b3, qaddr);
    #pragma unroll 4
    for (int nt = 0; nt < 32; nt++) {
        unsigned n0 = 0, n1 = 0, n2 = 0, n3 = 0;
        if (nt < 31) {
            ldsm_x4(n0, n1, n2, n3, qaddr + 8 * 80);
        }
        qaddr += 8 * 80;

        float acc[4] = {0.f, 0.f, 0.f, 0.f};
        mma16816(acc, afh[0], b0, b1);
        mma16816(acc, afh[1], b2, b3);
        mma16816(acc, afl[0], b0, b1);
        mma16816(acc, afl[1], b2, b3);

        const float2 bb = *(const float2*)(bias0 + nt * 8);
        float o00 = fmaf(s, acc[0], bb.x), o01 = fmaf(s, acc[1], bb.y);
        float o10 = fmaf(s, acc[2], bb.x), o11 = fmaf(s, acc[3], bb.y);
        stg_cs_f2(out0 + nt * 8, o00, o01);
        stg_cs_f2(out0 + 8 * VV + nt * 8, o10, o11);

        b0 = n0; b1 = n1; b2 = n2; b3 = n3;
    }
}

// Persistent FC worker. Workers on LSTM SMs sleep until ALL batches finish,
// then join the queue (tail help); others work immediately.
__device__ void fc_worker(const float* __restrict__ fcb, float* __restrict__ logits) {
    const int tid = threadIdx.x;
    if (tid == 0) {
        while (*(volatile unsigned*)&g_smid_ready < 8u) __nanosleep(100);
        __threadfence();
    }
    __syncthreads();

    const int mysm = (int)read_smid();
    int bad = 0;
    #pragma unroll
    for (int i = 0; i < 8; i++) bad |= (g_lstm_smid[i] == mysm);

    if (bad) {
        // Sleep (negligible issue pressure) until every LSTM batch is done,
        // then help drain the remaining tiles.
        if (tid == 0) {
            for (;;) {
                unsigned done = 0;
                #pragma unroll
                for (int i = 0; i < 8; i++)
                    done += (*(volatile unsigned*)&g_prog[i] >= (unsigned)SS);
                if (done == 8u) break;
                __nanosleep(2000);
            }
            __threadfence();
        }
        __syncthreads();
    }

    __shared__ unsigned sf;
    for (;;) {
        __syncthreads();                 // all warps done with previous tile's smem
        if (tid == 0) sf = atomicAdd(&g_tilectr, 1u);
        __syncthreads();
        unsigned f = sf;
        if (f >= (unsigned)NTILES) return;
        fc_tile((int)f, fcb, logits);
    }
}

__global__ void __launch_bounds__(256) k_fused(const float* __restrict__ b_hh,
                                               const float* __restrict__ fcb,
                                               float* __restrict__ out) {
    const int bid = blockIdx.x;
    if (bid < BB) { lstm_role(bid, b_hh, out); return; }
    fc_worker(fcb, out);
}

// ---------------- launch (4 launches; k_fused is 4th -> ncu capture lands on it) ----------------
extern "C" void kernel_launch(void* const* d_in, const int* in_sizes, int n_in,
                              void* d_out, int out_size) {
    const int*   x     = (const int*)  d_in[0];
    const float* emb_w = (const float*)d_in[1];
    const float* w_ih  = (const float*)d_in[2];
    const float* b_ih  = (const float*)d_in[3];
    const float* w_hh  = (const float*)d_in[4];
    const float* b_hh  = (const float*)d_in[5];
    const float* fc_w  = (const float*)d_in[6];
    const float* fc_b  = (const float*)d_in[7];
    float* out = (float*)d_out;

    k_reduce<<<256, 256>>>(emb_w, fc_w);
    k_final<<<1, 256>>>(w_ih, w_hh);                 // resets g_prog / smid / tile queue
    k_prep<<<2024, 256>>>(fc_w, x, emb_w, b_ih);     // fcq (0-999) + x_gates (1000-2023)
    k_fused<<<BB + 740, 256>>>(b_hh, fc_b, out);     // 8 LSTM + 740 persistent FC workers
}